// round 2
// baseline (speedup 1.0000x reference)
#include <cuda_runtime.h>
#include <cuda_bf16.h>

// out[n,p,d] = feat[n,p,d] * mean_m(task[n,m,p])
// n=32, m=16, p=1024, d=512
// task: [32, 16, 1024] float32   (d_in[0])
// feat: [32, 1024, 512] float32  (d_in[1])
// out:  [32, 1024, 512] float32

#define N_DIM 32
#define M_DIM 16
#define P_DIM 1024
#define D_DIM 512
#define ROWS_PER_BLOCK 2   // 2 (n,p) rows per block, 128 threads each

__global__ __launch_bounds__(256) void map_mean_scale_kernel(
    const float* __restrict__ task,
    const float* __restrict__ feat,
    float* __restrict__ out)
{
    // Each block covers ROWS_PER_BLOCK consecutive (n,p) rows.
    // threadIdx.x in [0,256): sub-row = tid/128, lane-in-row = tid%128.
    const int tid = threadIdx.x;
    const int sub = tid >> 7;          // 0 or 1
    const int lane = tid & 127;        // float4 index within the row

    const int np = blockIdx.x * ROWS_PER_BLOCK + sub;
    const int n = np >> 10;            // / P_DIM
    const int p = np & (P_DIM - 1);    // % P_DIM

    // Mean over m of task[n, m, p]. Warp-uniform addresses -> broadcast
    // loads; task is 2MB and stays L2-resident after the first wave.
    const float* t = task + (size_t)n * M_DIM * P_DIM + p;
    float s = 0.0f;
#pragma unroll
    for (int mm = 0; mm < M_DIM; ++mm)
        s += __ldg(t + mm * P_DIM);
    const float mean = s * (1.0f / (float)M_DIM);

    // 512 floats = 128 float4 per row; one float4 per thread.
    const size_t row = ((size_t)n * P_DIM + p) * D_DIM;
    const float4* f4 = reinterpret_cast<const float4*>(feat + row);
    float4* o4 = reinterpret_cast<float4*>(out + row);

    float4 v = f4[lane];
    v.x *= mean;
    v.y *= mean;
    v.z *= mean;
    v.w *= mean;
    o4[lane] = v;
}

extern "C" void kernel_launch(void* const* d_in, const int* in_sizes, int n_in,
                              void* d_out, int out_size)
{
    const float* task = (const float*)d_in[0];
    const float* feat = (const float*)d_in[1];
    float* out = (float*)d_out;

    dim3 grid((N_DIM * P_DIM) / ROWS_PER_BLOCK);  // 16384
    dim3 block(256);
    map_mean_scale_kernel<<<grid, block>>>(task, feat, out);
}

// round 8
// speedup vs baseline: 1.2779x; 1.2779x over previous
#include <cuda_runtime.h>
#include <cuda_bf16.h>

// out[n,p,d] = feat[n,p,d] * mean_m(task[n,m,p])
// n=32, m=16, p=1024, d=512
// task: [32, 16, 1024] float32   (d_in[0])
// feat: [32, 1024, 512] float32  (d_in[1])
// out:  [32, 1024, 512] float32

#define N_DIM 32
#define M_DIM 16
#define P_DIM 1024
#define D_DIM 512
#define WARPS_PER_BLOCK 8
#define V4_PER_THREAD 4   // 32 lanes * 4 float4 = 128 float4 = 512 floats = one row

__global__ __launch_bounds__(256) void map_mean_scale_kernel(
    const float* __restrict__ task,
    const float* __restrict__ feat,
    float* __restrict__ out)
{
    const int tid  = threadIdx.x;
    const int warp = tid >> 5;
    const int lane = tid & 31;

    // One warp per (n,p) row. np = n*1024 + p, feat row offset = np*512.
    const int np = blockIdx.x * WARPS_PER_BLOCK + warp;
    const int n  = np >> 10;           // / P_DIM
    const int p  = np & (P_DIM - 1);   // % P_DIM

    const size_t row = (size_t)np * D_DIM;
    const float4* f4 = reinterpret_cast<const float4*>(feat + row);
    float4*       o4 = reinterpret_cast<float4*>(out + row);

    // Streaming feat loads FIRST (independent, MLP=4), .cs so the 128MB
    // feat+out stream doesn't evict the 2MB task array from L2.
    float4 v[V4_PER_THREAD];
#pragma unroll
    for (int i = 0; i < V4_PER_THREAD; ++i)
        v[i] = __ldcs(f4 + lane + i * 32);

    // Mean over m of task[n,m,p]. Warp-uniform addresses -> one broadcast
    // request per load; 16 L2 requests per row (the minimum). Two partial
    // sums keep the add chain off the critical path of the last load.
    const float* t = task + (size_t)n * (M_DIM * P_DIM) + p;
    float s0 = 0.0f, s1 = 0.0f;
#pragma unroll
    for (int mm = 0; mm < M_DIM; mm += 2) {
        s0 += __ldg(t + mm * P_DIM);
        s1 += __ldg(t + (mm + 1) * P_DIM);
    }
    const float mean = (s0 + s1) * (1.0f / (float)M_DIM);

#pragma unroll
    for (int i = 0; i < V4_PER_THREAD; ++i) {
        float4 r = v[i];
        r.x *= mean; r.y *= mean; r.z *= mean; r.w *= mean;
        __stcs(o4 + lane + i * 32, r);
    }
}

extern "C" void kernel_launch(void* const* d_in, const int* in_sizes, int n_in,
                              void* d_out, int out_size)
{
    const float* task = (const float*)d_in[0];
    const float* feat = (const float*)d_in[1];
    float* out = (float*)d_out;

    dim3 grid((N_DIM * P_DIM) / WARPS_PER_BLOCK);  // 4096
    dim3 block(32 * WARPS_PER_BLOCK);              // 256
    map_mean_scale_kernel<<<grid, block>>>(task, feat, out);
}

// round 9
// speedup vs baseline: 1.3190x; 1.0322x over previous
#include <cuda_runtime.h>
#include <cuda_bf16.h>

// out[n,p,d] = feat[n,p,d] * mean_m(task[n,m,p])
// n=32, m=16, p=1024, d=512
// task: [32, 16, 1024] float32   (d_in[0])
// feat: [32, 1024, 512] float32  (d_in[1])
// out:  [32, 1024, 512] float32

#define N_DIM 32
#define M_DIM 16
#define P_DIM 1024
#define D_DIM 512
#define WARPS_PER_BLOCK 8
#define V4_PER_THREAD 4   // 32 lanes * 4 float4 = 128 float4 = 512 floats = one row

__global__ __launch_bounds__(256) void map_mean_scale_kernel(
    const float* __restrict__ task,
    const float* __restrict__ feat,
    float* __restrict__ out)
{
    const int tid  = threadIdx.x;
    const int warp = tid >> 5;
    const int lane = tid & 31;

    // One warp per (n,p) row. np = n*1024 + p, feat row offset = np*512.
    const int np = blockIdx.x * WARPS_PER_BLOCK + warp;
    const int n  = np >> 10;           // / P_DIM
    const int p  = np & (P_DIM - 1);   // % P_DIM

    const size_t row = (size_t)np * D_DIM;
    const float4* f4 = reinterpret_cast<const float4*>(feat + row);
    float4*       o4 = reinterpret_cast<float4*>(out + row);

    // Streaming feat loads FIRST (independent, MLP=4), .cs so the 128MB
    // feat+out stream doesn't evict the 2MB task array from L2.
    float4 v[V4_PER_THREAD];
#pragma unroll
    for (int i = 0; i < V4_PER_THREAD; ++i)
        v[i] = __ldcs(f4 + lane + i * 32);

    // Mean over m of task[n,m,p]. Warp-uniform addresses -> one broadcast
    // request per load; 16 L2 requests per row (the minimum). Two partial
    // sums keep the add chain off the critical path of the last load.
    const float* t = task + (size_t)n * (M_DIM * P_DIM) + p;
    float s0 = 0.0f, s1 = 0.0f;
#pragma unroll
    for (int mm = 0; mm < M_DIM; mm += 2) {
        s0 += __ldg(t + mm * P_DIM);
        s1 += __ldg(t + (mm + 1) * P_DIM);
    }
    const float mean = (s0 + s1) * (1.0f / (float)M_DIM);

#pragma unroll
    for (int i = 0; i < V4_PER_THREAD; ++i) {
        float4 r = v[i];
        r.x *= mean; r.y *= mean; r.z *= mean; r.w *= mean;
        __stcs(o4 + lane + i * 32, r);
    }
}

extern "C" void kernel_launch(void* const* d_in, const int* in_sizes, int n_in,
                              void* d_out, int out_size)
{
    const float* task = (const float*)d_in[0];
    const float* feat = (const float*)d_in[1];
    float* out = (float*)d_out;

    dim3 grid((N_DIM * P_DIM) / WARPS_PER_BLOCK);  // 4096
    dim3 block(32 * WARPS_PER_BLOCK);              // 256
    map_mean_scale_kernel<<<grid, block>>>(task, feat, out);
}